// round 8
// baseline (speedup 1.0000x reference)
#include <cuda_runtime.h>
#include <math.h>
#include <cstdint>

#define NROW 4096          // 64*64 legality cells per board
#define QDIM 256           // quality vector length
#define NEG_FILL -1000000.0f
#define EOS_COEF 0.25f
#define ROWS_PB 4          // rows per block (double-buffered pipeline)
#define MAXBLK 4096

// Dynamic shared layout (bytes)
#define OFF_SP    0            // float sP[2][4096]  (32768 B)
#define OFF_ST    32768        // float sT[2][4096]  (32768 B)
#define OFF_MBAR  65536        // u64 mbar[2]        (16 B)
#define OFF_SHD   65552        // double shd[8]      (64 B)
#define OFF_PQS   65616        // float pqs[256]     (1024 B)
#define OFF_TQS   66640        // float tqs[256]     (1024 B)
#define OFF_MT    67664        // unsigned maskT[128](512 B)
#define OFF_MP    68176        // unsigned maskP[128](512 B)
#define OFF_LINED 68688        // float lined[256]   (1024 B)
#define OFF_MATCH 69712        // uchar match[256]   (256 B)
#define OFF_RED   69968        // float red[8]       (32 B)
#define OFF_FLAG  70000        // unsigned lastFlag  (4 B)
#define SMEM_BYTES 70016

// Per-block partials + ticket (static globals — no allocation)
__device__ float    g_lab[MAXBLK];
__device__ float    g_ce [MAXBLK];
__device__ float    g_mse[MAXBLK];
__device__ unsigned g_count;   // zero-init; last block resets to 0

// spread 8 bits to every 4th bit position (bit i -> bit 4i)
__device__ __forceinline__ unsigned spread4(unsigned x) {
    x = (x | (x << 12)) & 0x000F000Fu;
    x = (x | (x << 6))  & 0x03030303u;
    x = (x | (x << 3))  & 0x11111111u;
    return x;
}
__device__ __forceinline__ float warpSum(float v) {
    #pragma unroll
    for (int o = 16; o; o >>= 1) v += __shfl_xor_sync(0xffffffffu, v, o);
    return v;
}
__device__ __forceinline__ float warpMax(float v) {
    #pragma unroll
    for (int o = 16; o; o >>= 1) v = fmaxf(v, __shfl_xor_sync(0xffffffffu, v, o));
    return v;
}
__device__ __forceinline__ double blockReduceSumD(double v, double* shd) {
    int lane = threadIdx.x & 31, warp = threadIdx.x >> 5;
    #pragma unroll
    for (int o = 16; o; o >>= 1) v += __shfl_down_sync(0xffffffffu, v, o);
    if (lane == 0) shd[warp] = v;
    __syncthreads();
    if (warp == 0) {
        v = (lane < 8) ? shd[lane] : 0.0;
        #pragma unroll
        for (int o = 4; o; o >>= 1) v += __shfl_down_sync(0xffffffffu, v, o);
        if (lane == 0) shd[0] = v;
    }
    __syncthreads();
    double r = shd[0];
    __syncthreads();
    return r;
}
__device__ __forceinline__ uint32_t smem_u32(const void* p) {
    return (uint32_t)__cvta_generic_to_shared(p);
}
__device__ __forceinline__ void mbar_wait(uint32_t mb, uint32_t parity) {
    uint32_t done;
    asm volatile(
        "{\n\t.reg .pred p;\n\t"
        "mbarrier.try_wait.parity.acquire.cta.shared::cta.b64 p, [%1], %2;\n\t"
        "selp.b32 %0, 1, 0, p;\n\t}"
        : "=r"(done) : "r"(mb), "r"(parity) : "memory");
    if (!done) {
        asm volatile(
            "{\n\t.reg .pred P1;\n\t"
            "WAIT_LOOP_%=:\n\t"
            "mbarrier.try_wait.parity.acquire.cta.shared::cta.b64 P1, [%0], %1, 0x989680;\n\t"
            "@P1 bra.uni WAIT_DONE_%=;\n\t"
            "bra.uni WAIT_LOOP_%=;\n\t"
            "WAIT_DONE_%=:\n\t}"
            :: "r"(mb), "r"(parity) : "memory");
    }
}
__device__ __forceinline__ void issue_row_copy(
    uint32_t mb, char* smem, int buf,
    const float* pl, const float* tl, int row)
{
    asm volatile("mbarrier.arrive.expect_tx.shared.b64 _, [%0], %1;"
                 :: "r"(mb), "r"(32768u) : "memory");
    const float* srcP = pl + (size_t)row * NROW;
    const float* srcT = tl + (size_t)row * NROW;
    asm volatile(
        "cp.async.bulk.shared::cluster.global.mbarrier::complete_tx::bytes"
        " [%0], [%1], %2, [%3];"
        :: "r"(smem_u32(smem + OFF_SP + buf * 16384)), "l"(srcP),
           "r"(16384u), "r"(mb) : "memory");
    asm volatile(
        "cp.async.bulk.shared::cluster.global.mbarrier::complete_tx::bytes"
        " [%0], [%1], %2, [%3];"
        :: "r"(smem_u32(smem + OFF_ST + buf * 16384)), "l"(srcT),
           "r"(16384u), "r"(mb) : "memory");
}

__global__ __launch_bounds__(256) void crit_kernel(
    const float* __restrict__ pl,     // pred_legal  [B,4096]
    const float* __restrict__ tl,     // target_legal[B,4096]
    const float4* __restrict__ pq4,   // pred_q      [B*64] float4
    const float4* __restrict__ tq4,   // target_q    [B*64] float4
    float* __restrict__ out, int B, int nblk)
{
    extern __shared__ char smem[];
    float*    pqs   = (float*)(smem + OFF_PQS);
    float*    tqs   = (float*)(smem + OFF_TQS);
    unsigned* maskT = (unsigned*)(smem + OFF_MT);
    unsigned* maskP = (unsigned*)(smem + OFF_MP);
    float*    lined = (float*)(smem + OFF_LINED);
    unsigned char* match = (unsigned char*)(smem + OFF_MATCH);
    float*    red   = (float*)(smem + OFF_RED);
    double*   shd   = (double*)(smem + OFF_SHD);
    unsigned* lastFlag = (unsigned*)(smem + OFF_FLAG);

    const int r0 = blockIdx.x * ROWS_PB;
    const int w = threadIdx.x >> 5, l = threadIdx.x & 31;
    const uint32_t mb0 = smem_u32(smem + OFF_MBAR);
    const uint32_t mb1 = mb0 + 8;

    if (threadIdx.x == 0) {
        asm volatile("mbarrier.init.shared.b64 [%0], %1;" :: "r"(mb0), "r"(1u) : "memory");
        asm volatile("mbarrier.init.shared.b64 [%0], %1;" :: "r"(mb1), "r"(1u) : "memory");
    }
    __syncthreads();
    if (threadIdx.x == 0) {
        issue_row_copy(mb0, smem, 0, pl, tl, r0);
        issue_row_copy(mb1, smem, 1, pl, tl, r0 + 1);
    }

    float accLab = 0.f, accCe = 0.f, accMse = 0.f;   // live in thread 0 only

    for (int r = 0; r < ROWS_PB; r++) {
        const int b = r0 + r;
        const int buf = r & 1;
        const uint32_t mb = buf ? mb1 : mb0;
        const uint32_t parity = (r >> 1) & 1;

        // prefetch quality vectors into registers (overlaps the copy wait)
        float4 pqv = make_float4(0,0,0,0), tqv = make_float4(0,0,0,0);
        if (threadIdx.x < 64)       pqv = __ldg(pq4 + (size_t)b * 64 + threadIdx.x);
        else if (threadIdx.x < 128) tqv = __ldg(tq4 + (size_t)b * 64 + (threadIdx.x - 64));

        mbar_wait(mb, parity);

        if (threadIdx.x < 64)       ((float4*)pqs)[threadIdx.x] = pqv;
        else if (threadIdx.x < 128) ((float4*)tqs)[threadIdx.x - 64] = tqv;

        // ---- BCE + ballot masks from shared buffer ----
        const float4* sP4 = (const float4*)(smem + OFF_SP + buf * 16384);
        const float4* sT4 = (const float4*)(smem + OFF_ST + buf * 16384);
        float acc = 0.f;
        #pragma unroll
        for (int i = 0; i < 4; i++) {
            int idx = w * 128 + i * 32 + l;
            float4 pv = sP4[idx];
            float4 tv = sT4[idx];
            float px[4] = {pv.x, pv.y, pv.z, pv.w};
            float tx[4] = {tv.x, tv.y, tv.z, tv.w};
            bool pt[4], pp[4];
            #pragma unroll
            for (int j = 0; j < 4; j++) {
                float x = px[j], tg = tx[j];
                float sp  = __logf(1.f + __expf(-fabsf(x)));   // fast ok in BCE (R3)
                float bce = fmaxf(x, 0.f) - x * tg + sp;
                acc += (tg == 0.f ? EOS_COEF : 1.f) * bce;
                pt[j] = (tg == 1.f);
                pp[j] = (x  > 0.f);
            }
            unsigned bT0 = __ballot_sync(0xffffffffu, pt[0]);
            unsigned bT1 = __ballot_sync(0xffffffffu, pt[1]);
            unsigned bT2 = __ballot_sync(0xffffffffu, pt[2]);
            unsigned bT3 = __ballot_sync(0xffffffffu, pt[3]);
            unsigned bP0 = __ballot_sync(0xffffffffu, pp[0]);
            unsigned bP1 = __ballot_sync(0xffffffffu, pp[1]);
            unsigned bP2 = __ballot_sync(0xffffffffu, pp[2]);
            unsigned bP3 = __ballot_sync(0xffffffffu, pp[3]);
            int base = w * 16 + i * 4;
            if (l < 4) {
                unsigned vT = (l == 0) ? bT0 : (l == 1) ? bT1 : (l == 2) ? bT2 : bT3;
                maskT[base + l] = vT;
            } else if (l < 8) {
                int j = l - 4;
                unsigned vP = (j == 0) ? bP0 : (j == 1) ? bP1 : (j == 2) ? bP2 : bP3;
                maskP[base + j] = vP;
            }
        }
        acc = warpSum(acc);
        if (l == 0) red[w] = acc;
        __syncthreads();   // (A) buffer reads + mask/pq stores complete

        // re-issue this buffer for row r+2 (keeps the copy stream continuous)
        if (threadIdx.x == 0 && r + 2 < ROWS_PB)
            issue_row_copy(mb, smem, buf, pl, tl, b + 2);

        // ---- lineup: warp 0 only ----
        if (w == 0) {
            uint4 WT = ((const uint4*)maskT)[l];
            uint4 WP = ((const uint4*)maskP)[l];

            #pragma unroll
            for (int j = 0; j < 8; j++) {
                lined[l * 8 + j] = NEG_FILL;
                match[l * 8 + j] = 0;
            }

            unsigned mT[4], mP[4];
            #pragma unroll
            for (int k = 0; k < 4; k++) {
                unsigned s = 8 * k;
                mT[k] = spread4((WT.x >> s) & 0xFFu)
                      | (spread4((WT.y >> s) & 0xFFu) << 1)
                      | (spread4((WT.z >> s) & 0xFFu) << 2)
                      | (spread4((WT.w >> s) & 0xFFu) << 3);
                mP[k] = spread4((WP.x >> s) & 0xFFu)
                      | (spread4((WP.y >> s) & 0xFFu) << 1)
                      | (spread4((WP.z >> s) & 0xFFu) << 2)
                      | (spread4((WP.w >> s) & 0xFFu) << 3);
            }

            int cT = 0, cP = 0;
            #pragma unroll
            for (int k = 0; k < 4; k++) { cT += __popc(mT[k]); cP += __popc(mP[k]); }
            int sTc = cT, sPc = cP;
            #pragma unroll
            for (int o = 1; o < 32; o <<= 1) {
                int vT = __shfl_up_sync(0xffffffffu, sTc, o);
                int vP = __shfl_up_sync(0xffffffffu, sPc, o);
                if (l >= o) { sTc += vT; sPc += vP; }
            }
            int tIdx  = sTc - cT;
            int pBase = sPc - cP;
            __syncwarp();

            #pragma unroll
            for (int k = 0; k < 4; k++) {
                unsigned m = mT[k], p = mP[k];
                while (m) {
                    int bit = __ffs(m) - 1;
                    m &= m - 1;
                    if ((p >> bit) & 1u) {
                        int pi = pBase + __popc(p & ((1u << bit) - 1u));
                        if (pi < QDIM - 1 && tIdx < QDIM - 1) {
                            lined[tIdx] = pqs[pi];
                            match[tIdx] = 1;
                        }
                    }
                    tIdx++;
                }
                pBase += __popc(p);
            }
            __syncwarp();

            // logsumexp over lined[0..254] — PRECISE expf/logf (CE x200 sensitive)
            float vals[8];
            float mx = -INFINITY;
            #pragma unroll
            for (int j = 0; j < 8; j++) {
                vals[j] = lined[l * 8 + j];
                mx = fmaxf(mx, vals[j]);
            }
            mx = warpMax(mx);
            float es = 0.f;
            #pragma unroll
            for (int j = 0; j < 8; j++)
                if (l * 8 + j < QDIM - 1) es += expf(vals[j] - mx);
            es = warpSum(es);
            float lse = mx + logf(es);

            float wsum = 0.f, dot = 0.f;
            #pragma unroll
            for (int j = 0; j < 8; j++) {
                int idx = l * 8 + j;
                if (idx < QDIM - 1) {
                    float wq = tqs[idx] * (float)match[idx];
                    wsum += wq;
                    dot  += wq * (vals[j] - lse);
                }
            }
            wsum = warpSum(wsum);
            dot  = warpSum(dot);

            if (l == 0) {
                accCe  += -dot / (wsum + 1e-10f);
                float dq = pqs[QDIM - 1] - tqs[QDIM - 1];
                accMse += dq * dq;
                float lab = 0.f;
                #pragma unroll
                for (int i = 0; i < 8; i++) lab += red[i];
                accLab += lab;
            }
        }
        __syncthreads();   // (B) lineup done; masks/pqs reusable next row
    }

    // ---- per-block partials + ticket ----
    if (threadIdx.x == 0) {
        g_lab[blockIdx.x] = accLab;
        g_ce [blockIdx.x] = accCe;
        g_mse[blockIdx.x] = accMse;
        __threadfence();
        unsigned old = atomicAdd(&g_count, 1u);
        *lastFlag = (old == (unsigned)(nblk - 1)) ? 1u : 0u;
    }
    __syncthreads();

    if (*lastFlag) {
        __threadfence();
        double sLab = 0.0, sCe = 0.0, sMse = 0.0;
        for (int i = threadIdx.x; i < nblk; i += 256) {
            sLab += (double)g_lab[i];
            sCe  += (double)g_ce[i];
            sMse += (double)g_mse[i];
        }
        sLab = blockReduceSumD(sLab, shd);
        sCe  = blockReduceSumD(sCe,  shd);
        sMse = blockReduceSumD(sMse, shd);
        if (threadIdx.x == 0) {
            double loss_labels = sLab / ((double)B * (double)NROW);
            double loss_ce     = sCe / (double)(QDIM - 1);
            double loss_mse    = sMse / (double)B;
            out[0] = (float)loss_labels;
            out[1] = (float)(loss_ce * 200.0 + loss_mse);
            g_count = 0;   // reset for next graph replay
        }
    }
}

extern "C" void kernel_launch(void* const* d_in, const int* in_sizes, int n_in,
                              void* d_out, int out_size) {
    const float* pred_legal   = (const float*)d_in[0];
    const float* pred_q       = (const float*)d_in[1];
    const float* target_legal = (const float*)d_in[2];
    const float* target_q     = (const float*)d_in[3];
    float* out = (float*)d_out;

    int B = in_sizes[1] / QDIM;      // 4096
    int nblk = B / ROWS_PB;          // 1024

    static bool attrSet = false;
    if (!attrSet) {
        cudaFuncSetAttribute(crit_kernel,
                             cudaFuncAttributeMaxDynamicSharedMemorySize, SMEM_BYTES);
        attrSet = true;
    }

    crit_kernel<<<nblk, 256, SMEM_BYTES>>>(pred_legal, target_legal,
                                           (const float4*)pred_q,
                                           (const float4*)target_q,
                                           out, B, nblk);
}

// round 10
// speedup vs baseline: 1.4881x; 1.4881x over previous
#include <cuda_runtime.h>
#include <math.h>
#include <cstdint>

#define NROW 4096          // 64*64 legality cells per board
#define QDIM 256           // quality vector length
#define NEG_FILL -1000000.0f
#define EOS_COEF 0.25f
#define ROWS_PB 2          // rows per block
#define NSTAGE  (2 * ROWS_PB)
#define HALF    2048       // elements per half-row
#define HALF_B  8192       // bytes per half-row
#define MAXBLK 4096

// Dynamic shared layout (bytes) — all offsets 16B-aligned
#define OFF_SP    0            // float sP[2][2048]  (16384 B)
#define OFF_ST    16384        // float sT[2][2048]  (16384 B)
#define OFF_MBAR  32768        // u64 mbar[2]        (16 B)
#define OFF_SHD   32784        // double shd[8]      (64 B)
#define OFF_PQS   32848        // float pqs[256]     (1024 B)
#define OFF_TQS   33872        // float tqs[256]     (1024 B)
#define OFF_MT    34896        // unsigned maskT[128](512 B)
#define OFF_MP    35408        // unsigned maskP[128](512 B)
#define OFF_LINED 35920        // float lined[256]   (1024 B)
#define OFF_MATCH 36944        // uchar match[256]   (256 B)
#define OFF_RED   37200        // float red[8]       (32 B)
#define OFF_FLAG  37232        // unsigned lastFlag  (16 B)
#define SMEM_BYTES 37248

// Per-block partials + ticket (static globals — no allocation)
__device__ float    g_lab[MAXBLK];
__device__ float    g_ce [MAXBLK];
__device__ float    g_mse[MAXBLK];
__device__ unsigned g_count;   // zero-init; last block resets to 0

// spread 8 bits to every 4th bit position (bit i -> bit 4i)
__device__ __forceinline__ unsigned spread4(unsigned x) {
    x = (x | (x << 12)) & 0x000F000Fu;
    x = (x | (x << 6))  & 0x03030303u;
    x = (x | (x << 3))  & 0x11111111u;
    return x;
}
__device__ __forceinline__ float warpSum(float v) {
    #pragma unroll
    for (int o = 16; o; o >>= 1) v += __shfl_xor_sync(0xffffffffu, v, o);
    return v;
}
__device__ __forceinline__ float warpMax(float v) {
    #pragma unroll
    for (int o = 16; o; o >>= 1) v = fmaxf(v, __shfl_xor_sync(0xffffffffu, v, o));
    return v;
}
__device__ __forceinline__ double blockReduceSumD(double v, double* shd) {
    int lane = threadIdx.x & 31, warp = threadIdx.x >> 5;
    #pragma unroll
    for (int o = 16; o; o >>= 1) v += __shfl_down_sync(0xffffffffu, v, o);
    if (lane == 0) shd[warp] = v;
    __syncthreads();
    if (warp == 0) {
        v = (lane < 8) ? shd[lane] : 0.0;
        #pragma unroll
        for (int o = 4; o; o >>= 1) v += __shfl_down_sync(0xffffffffu, v, o);
        if (lane == 0) shd[0] = v;
    }
    __syncthreads();
    double r = shd[0];
    __syncthreads();
    return r;
}
__device__ __forceinline__ uint32_t smem_u32(const void* p) {
    return (uint32_t)__cvta_generic_to_shared(p);
}
__device__ __forceinline__ void mbar_wait(uint32_t mb, uint32_t parity) {
    uint32_t done;
    asm volatile(
        "{\n\t.reg .pred p;\n\t"
        "mbarrier.try_wait.parity.acquire.cta.shared::cta.b64 p, [%1], %2;\n\t"
        "selp.b32 %0, 1, 0, p;\n\t}"
        : "=r"(done) : "r"(mb), "r"(parity) : "memory");
    if (!done) {
        asm volatile(
            "{\n\t.reg .pred P1;\n\t"
            "WAIT_LOOP_%=:\n\t"
            "mbarrier.try_wait.parity.acquire.cta.shared::cta.b64 P1, [%0], %1, 0x989680;\n\t"
            "@P1 bra.uni WAIT_DONE_%=;\n\t"
            "bra.uni WAIT_LOOP_%=;\n\t"
            "WAIT_DONE_%=:\n\t}"
            :: "r"(mb), "r"(parity) : "memory");
    }
}
// copy half-row `h` of `row` into buffer `buf` (8 KB P + 8 KB T, expect 16 KB)
__device__ __forceinline__ void issue_half_copy(
    uint32_t mb, char* smem, int buf,
    const float* pl, const float* tl, int row, int h)
{
    asm volatile("mbarrier.arrive.expect_tx.shared.b64 _, [%0], %1;"
                 :: "r"(mb), "r"((unsigned)(2 * HALF_B)) : "memory");
    const float* srcP = pl + (size_t)row * NROW + h * HALF;
    const float* srcT = tl + (size_t)row * NROW + h * HALF;
    asm volatile(
        "cp.async.bulk.shared::cluster.global.mbarrier::complete_tx::bytes"
        " [%0], [%1], %2, [%3];"
        :: "r"(smem_u32(smem + OFF_SP + buf * HALF_B)), "l"(srcP),
           "r"((unsigned)HALF_B), "r"(mb) : "memory");
    asm volatile(
        "cp.async.bulk.shared::cluster.global.mbarrier::complete_tx::bytes"
        " [%0], [%1], %2, [%3];"
        :: "r"(smem_u32(smem + OFF_ST + buf * HALF_B)), "l"(srcT),
           "r"((unsigned)HALF_B), "r"(mb) : "memory");
}

__global__ __launch_bounds__(256, 6) void crit_kernel(
    const float* __restrict__ pl,     // pred_legal  [B,4096]
    const float* __restrict__ tl,     // target_legal[B,4096]
    const float4* __restrict__ pq4,   // pred_q      [B*64] float4
    const float4* __restrict__ tq4,   // target_q    [B*64] float4
    float* __restrict__ out, int B, int nblk)
{
    extern __shared__ char smem[];
    float*    pqs   = (float*)(smem + OFF_PQS);
    float*    tqs   = (float*)(smem + OFF_TQS);
    unsigned* maskT = (unsigned*)(smem + OFF_MT);
    unsigned* maskP = (unsigned*)(smem + OFF_MP);
    float*    lined = (float*)(smem + OFF_LINED);
    unsigned char* match = (unsigned char*)(smem + OFF_MATCH);
    float*    red   = (float*)(smem + OFF_RED);
    double*   shd   = (double*)(smem + OFF_SHD);
    unsigned* lastFlag = (unsigned*)(smem + OFF_FLAG);

    const int r0 = blockIdx.x * ROWS_PB;
    const int w = threadIdx.x >> 5, l = threadIdx.x & 31;
    const uint32_t mb0 = smem_u32(smem + OFF_MBAR);
    const uint32_t mb1 = mb0 + 8;

    if (threadIdx.x == 0) {
        asm volatile("mbarrier.init.shared.b64 [%0], %1;" :: "r"(mb0), "r"(1u) : "memory");
        asm volatile("mbarrier.init.shared.b64 [%0], %1;" :: "r"(mb1), "r"(1u) : "memory");
    }
    __syncthreads();
    if (threadIdx.x == 0) {
        issue_half_copy(mb0, smem, 0, pl, tl, r0, 0);   // stage 0
        issue_half_copy(mb1, smem, 1, pl, tl, r0, 1);   // stage 1
    }

    float accLab = 0.f, accCe = 0.f, accMse = 0.f;   // meaningful in thread 0

    #pragma unroll
    for (int s = 0; s < NSTAGE; s++) {
        const int r = s >> 1;          // row within block
        const int h = s & 1;           // half within row
        const int b = r0 + r;          // global row
        const int buf = s & 1;         // buffers alternate per stage
        const uint32_t mb = buf ? mb1 : mb0;
        const uint32_t parity = (s >> 1) & 1;

        // prefetch quality vectors (first half of each row) — overlaps copy wait
        float4 pqv = make_float4(0,0,0,0), tqv = make_float4(0,0,0,0);
        if (h == 0) {
            if (threadIdx.x < 64)       pqv = __ldg(pq4 + (size_t)b * 64 + threadIdx.x);
            else if (threadIdx.x < 128) tqv = __ldg(tq4 + (size_t)b * 64 + (threadIdx.x - 64));
        }

        mbar_wait(mb, parity);

        if (h == 0) {
            if (threadIdx.x < 64)       ((float4*)pqs)[threadIdx.x] = pqv;
            else if (threadIdx.x < 128) ((float4*)tqs)[threadIdx.x - 64] = tqv;
        }

        // ---- stream this half from shared: warp w covers 256 elements ----
        const float4* sP4 = (const float4*)(smem + OFF_SP + buf * HALF_B);
        const float4* sT4 = (const float4*)(smem + OFF_ST + buf * HALF_B);
        float acc = 0.f;
        #pragma unroll
        for (int i = 0; i < 2; i++) {
            int idx = w * 64 + i * 32 + l;
            float4 pv = sP4[idx];
            float4 tv = sT4[idx];
            float px[4] = {pv.x, pv.y, pv.z, pv.w};
            float tx[4] = {tv.x, tv.y, tv.z, tv.w};
            bool pt[4], pp[4];
            #pragma unroll
            for (int j = 0; j < 4; j++) {
                float x = px[j], tg = tx[j];
                float sp  = __logf(1.f + __expf(-fabsf(x)));   // fast ok in BCE (R3)
                float bce = fmaxf(x, 0.f) - x * tg + sp;
                acc += (tg == 0.f ? EOS_COEF : 1.f) * bce;
                pt[j] = (tg == 1.f);
                pp[j] = (x  > 0.f);
            }
            unsigned bT0 = __ballot_sync(0xffffffffu, pt[0]);
            unsigned bT1 = __ballot_sync(0xffffffffu, pt[1]);
            unsigned bT2 = __ballot_sync(0xffffffffu, pt[2]);
            unsigned bT3 = __ballot_sync(0xffffffffu, pt[3]);
            unsigned bP0 = __ballot_sync(0xffffffffu, pp[0]);
            unsigned bP1 = __ballot_sync(0xffffffffu, pp[1]);
            unsigned bP2 = __ballot_sync(0xffffffffu, pp[2]);
            unsigned bP3 = __ballot_sync(0xffffffffu, pp[3]);
            // chunk c of 128 row elements = h*16 + w*2 + i; words c*4+j, bit l
            int base = (h * 16 + w * 2 + i) * 4;
            if (l < 4) {
                unsigned vT = (l == 0) ? bT0 : (l == 1) ? bT1 : (l == 2) ? bT2 : bT3;
                maskT[base + l] = vT;
            } else if (l < 8) {
                int j = l - 4;
                unsigned vP = (j == 0) ? bP0 : (j == 1) ? bP1 : (j == 2) ? bP2 : bP3;
                maskP[base + j] = vP;
            }
        }
        acc = warpSum(acc);
        // per-warp row BCE: set at h==0, accumulate at h==1 (same thread writes)
        if (l == 0) {
            if (h == 0) red[w] = acc;
            else        red[w] += acc;
        }
        __syncthreads();   // (A) buffer consumed; masks/pq/red visible

        // re-issue this buffer for stage s+2 (keeps copy stream continuous)
        if (threadIdx.x == 0 && s + 2 < NSTAGE)
            issue_half_copy(mb, smem, buf, pl, tl, r0 + ((s + 2) >> 1), (s + 2) & 1);

        if (h == 1) {
            // ---- lineup for row b: warp 0 only ----
            if (w == 0) {
                uint4 WT = ((const uint4*)maskT)[l];
                uint4 WP = ((const uint4*)maskP)[l];

                #pragma unroll
                for (int j = 0; j < 8; j++) {
                    lined[l * 8 + j] = NEG_FILL;
                    match[l * 8 + j] = 0;
                }

                unsigned mT[4], mP[4];
                #pragma unroll
                for (int k = 0; k < 4; k++) {
                    unsigned sh = 8 * k;
                    mT[k] = spread4((WT.x >> sh) & 0xFFu)
                          | (spread4((WT.y >> sh) & 0xFFu) << 1)
                          | (spread4((WT.z >> sh) & 0xFFu) << 2)
                          | (spread4((WT.w >> sh) & 0xFFu) << 3);
                    mP[k] = spread4((WP.x >> sh) & 0xFFu)
                          | (spread4((WP.y >> sh) & 0xFFu) << 1)
                          | (spread4((WP.z >> sh) & 0xFFu) << 2)
                          | (spread4((WP.w >> sh) & 0xFFu) << 3);
                }

                int cT = 0, cP = 0;
                #pragma unroll
                for (int k = 0; k < 4; k++) { cT += __popc(mT[k]); cP += __popc(mP[k]); }
                int sTc = cT, sPc = cP;
                #pragma unroll
                for (int o = 1; o < 32; o <<= 1) {
                    int vT = __shfl_up_sync(0xffffffffu, sTc, o);
                    int vP = __shfl_up_sync(0xffffffffu, sPc, o);
                    if (l >= o) { sTc += vT; sPc += vP; }
                }
                int tIdx  = sTc - cT;
                int pBase = sPc - cP;
                __syncwarp();

                #pragma unroll
                for (int k = 0; k < 4; k++) {
                    unsigned m = mT[k], p = mP[k];
                    while (m) {
                        int bit = __ffs(m) - 1;
                        m &= m - 1;
                        if ((p >> bit) & 1u) {
                            int pi = pBase + __popc(p & ((1u << bit) - 1u));
                            if (pi < QDIM - 1 && tIdx < QDIM - 1) {
                                lined[tIdx] = pqs[pi];
                                match[tIdx] = 1;
                            }
                        }
                        tIdx++;
                    }
                    pBase += __popc(p);
                }
                __syncwarp();

                // logsumexp over lined[0..254] — PRECISE expf/logf (CE x200)
                float vals[8];
                float mx = -INFINITY;
                #pragma unroll
                for (int j = 0; j < 8; j++) {
                    vals[j] = lined[l * 8 + j];
                    mx = fmaxf(mx, vals[j]);
                }
                mx = warpMax(mx);
                float es = 0.f;
                #pragma unroll
                for (int j = 0; j < 8; j++)
                    if (l * 8 + j < QDIM - 1) es += expf(vals[j] - mx);
                es = warpSum(es);
                float lse = mx + logf(es);

                float wsum = 0.f, dot = 0.f;
                #pragma unroll
                for (int j = 0; j < 8; j++) {
                    int idx = l * 8 + j;
                    if (idx < QDIM - 1) {
                        float wq = tqs[idx] * (float)match[idx];
                        wsum += wq;
                        dot  += wq * (vals[j] - lse);
                    }
                }
                wsum = warpSum(wsum);
                dot  = warpSum(dot);

                if (l == 0) {
                    accCe  += -dot / (wsum + 1e-10f);
                    float dq = pqs[QDIM - 1] - tqs[QDIM - 1];
                    accMse += dq * dq;
                    float lab = 0.f;
                    #pragma unroll
                    for (int i = 0; i < 8; i++) lab += red[i];
                    accLab += lab;
                }
            }
            __syncthreads();   // (B) lineup done; masks/pqs reusable next row
        }
    }

    // ---- per-block partials + ticket ----
    if (threadIdx.x == 0) {
        g_lab[blockIdx.x] = accLab;
        g_ce [blockIdx.x] = accCe;
        g_mse[blockIdx.x] = accMse;
        __threadfence();
        unsigned old = atomicAdd(&g_count, 1u);
        *lastFlag = (old == (unsigned)(nblk - 1)) ? 1u : 0u;
    }
    __syncthreads();

    if (*lastFlag) {
        __threadfence();
        double sLab = 0.0, sCe = 0.0, sMse = 0.0;
        for (int i = threadIdx.x; i < nblk; i += 256) {
            sLab += (double)g_lab[i];
            sCe  += (double)g_ce[i];
            sMse += (double)g_mse[i];
        }
        sLab = blockReduceSumD(sLab, shd);
        sCe  = blockReduceSumD(sCe,  shd);
        sMse = blockReduceSumD(sMse, shd);
        if (threadIdx.x == 0) {
            double loss_labels = sLab / ((double)B * (double)NROW);
            double loss_ce     = sCe / (double)(QDIM - 1);
            double loss_mse    = sMse / (double)B;
            out[0] = (float)loss_labels;
            out[1] = (float)(loss_ce * 200.0 + loss_mse);
            g_count = 0;   // reset for next graph replay
        }
    }
}

extern "C" void kernel_launch(void* const* d_in, const int* in_sizes, int n_in,
                              void* d_out, int out_size) {
    const float* pred_legal   = (const float*)d_in[0];
    const float* pred_q       = (const float*)d_in[1];
    const float* target_legal = (const float*)d_in[2];
    const float* target_q     = (const float*)d_in[3];
    float* out = (float*)d_out;

    int B = in_sizes[1] / QDIM;      // 4096
    int nblk = B / ROWS_PB;          // 2048

    static bool attrSet = false;
    if (!attrSet) {
        cudaFuncSetAttribute(crit_kernel,
                             cudaFuncAttributeMaxDynamicSharedMemorySize, SMEM_BYTES);
        attrSet = true;
    }

    crit_kernel<<<nblk, 256, SMEM_BYTES>>>(pred_legal, target_legal,
                                           (const float4*)pred_q,
                                           (const float4*)target_q,
                                           out, B, nblk);
}

// round 11
// speedup vs baseline: 1.8071x; 1.2144x over previous
#include <cuda_runtime.h>
#include <math.h>
#include <cstdint>

#define NROW 4096          // 64*64 legality cells per board
#define QDIM 256           // quality vector length
#define NEG_FILL -1000000.0f
#define EOS_COEF 0.25f
#define ROWS_PB 8          // rows per block = warps per block
#define MAXBLK 4096

// Per-block partials + ticket (static globals — no allocation)
__device__ float    g_lab[MAXBLK];
__device__ float    g_ce [MAXBLK];
__device__ float    g_mse[MAXBLK];
__device__ unsigned g_count;   // zero-init; last block resets to 0

// spread 8 bits to every 4th bit position (bit i -> bit 4i)
__device__ __forceinline__ unsigned spread4(unsigned x) {
    x = (x | (x << 12)) & 0x000F000Fu;
    x = (x | (x << 6))  & 0x03030303u;
    x = (x | (x << 3))  & 0x11111111u;
    return x;
}
__device__ __forceinline__ float warpSum(float v) {
    #pragma unroll
    for (int o = 16; o; o >>= 1) v += __shfl_xor_sync(0xffffffffu, v, o);
    return v;
}
__device__ __forceinline__ float warpMax(float v) {
    #pragma unroll
    for (int o = 16; o; o >>= 1) v = fmaxf(v, __shfl_xor_sync(0xffffffffu, v, o));
    return v;
}
__device__ __forceinline__ double blockReduceSumD(double v, double* shd) {
    int lane = threadIdx.x & 31, warp = threadIdx.x >> 5;
    #pragma unroll
    for (int o = 16; o; o >>= 1) v += __shfl_down_sync(0xffffffffu, v, o);
    if (lane == 0) shd[warp] = v;
    __syncthreads();
    if (warp == 0) {
        v = (lane < 8) ? shd[lane] : 0.0;
        #pragma unroll
        for (int o = 4; o; o >>= 1) v += __shfl_down_sync(0xffffffffu, v, o);
        if (lane == 0) shd[0] = v;
    }
    __syncthreads();
    double r = shd[0];
    __syncthreads();
    return r;
}

// One block = 8 rows. Phase 1: all warps stream all rows (barrier-free).
// Phase 2: warp w runs the full lineup for row w (8 lineups in parallel).
__global__ __launch_bounds__(256, 6) void crit_kernel(
    const float* __restrict__ pl,     // pred_legal  [B,4096]
    const float* __restrict__ tl,     // target_legal[B,4096]
    const float4* __restrict__ pq4,   // pred_q      [B*64] float4
    const float4* __restrict__ tq4,   // target_q    [B*64] float4
    float* __restrict__ out, int B, int nblk)
{
    const int r0 = blockIdx.x * ROWS_PB;
    const int w = threadIdx.x >> 5, l = threadIdx.x & 31;
    const int t = threadIdx.x;

    __shared__ alignas(16) unsigned maskT[ROWS_PB * 128];   // 4 KB (ballot order)
    __shared__ alignas(16) unsigned maskP[ROWS_PB * 128];   // 4 KB
    __shared__ alignas(16) float pqs[ROWS_PB * QDIM];       // 8 KB
    __shared__ alignas(16) float tqs[ROWS_PB * QDIM];       // 8 KB
    __shared__ alignas(16) float lined[ROWS_PB * QDIM];     // 8 KB
    __shared__ unsigned char match[ROWS_PB * QDIM];         // 2 KB
    __shared__ float rowCe[ROWS_PB], rowMse[ROWS_PB];
    __shared__ double shd[8];
    __shared__ unsigned lastFlag;

    // ---- stage quality vectors: 8 rows x 64 float4 = 512 float4, 2/thread ----
    {
        const float4* src = pq4 + (size_t)r0 * 64;
        ((float4*)pqs)[t]       = __ldg(src + t);
        ((float4*)pqs)[t + 256] = __ldg(src + t + 256);
        const float4* srcT = tq4 + (size_t)r0 * 64;
        ((float4*)tqs)[t]       = __ldg(srcT + t);
        ((float4*)tqs)[t + 256] = __ldg(srcT + t + 256);
    }

    // ---- phase 1: stream 8 rows, no block barriers ----
    float accBce = 0.f;
    for (int r = 0; r < ROWS_PB; r++) {
        const size_t rowOff = (size_t)(r0 + r) * 1024;  // in float4 units
        const float4* pl4 = (const float4*)pl + rowOff;
        const float4* tl4 = (const float4*)tl + rowOff;
        #pragma unroll
        for (int i = 0; i < 4; i++) {
            int idx = w * 128 + i * 32 + l;             // lane-coalesced
            float4 pv = __ldg(pl4 + idx);
            float4 tv = __ldg(tl4 + idx);
            float px[4] = {pv.x, pv.y, pv.z, pv.w};
            float tx[4] = {tv.x, tv.y, tv.z, tv.w};
            bool pt[4], pp[4];
            #pragma unroll
            for (int j = 0; j < 4; j++) {
                float x = px[j], tg = tx[j];
                float sp  = __logf(1.f + __expf(-fabsf(x)));   // fast ok in BCE (R3)
                float bce = fmaxf(x, 0.f) - x * tg + sp;
                accBce += (tg == 0.f ? EOS_COEF : 1.f) * bce;
                pt[j] = (tg == 1.f);
                pp[j] = (x  > 0.f);
            }
            unsigned bT0 = __ballot_sync(0xffffffffu, pt[0]);
            unsigned bT1 = __ballot_sync(0xffffffffu, pt[1]);
            unsigned bT2 = __ballot_sync(0xffffffffu, pt[2]);
            unsigned bT3 = __ballot_sync(0xffffffffu, pt[3]);
            unsigned bP0 = __ballot_sync(0xffffffffu, pp[0]);
            unsigned bP1 = __ballot_sync(0xffffffffu, pp[1]);
            unsigned bP2 = __ballot_sync(0xffffffffu, pp[2]);
            unsigned bP3 = __ballot_sync(0xffffffffu, pp[3]);
            // chunk c = w*4 + i of row r; word c*4+j, bit l = element c*128+4l+j
            int base = r * 128 + (w * 4 + i) * 4;
            if (l < 4) {
                unsigned vT = (l == 0) ? bT0 : (l == 1) ? bT1 : (l == 2) ? bT2 : bT3;
                maskT[base + l] = vT;
            } else if (l < 8) {
                int j = l - 4;
                unsigned vP = (j == 0) ? bP0 : (j == 1) ? bP1 : (j == 2) ? bP2 : bP3;
                maskP[base + j] = vP;
            }
        }
    }
    __syncthreads();   // masks + staged quality vectors visible

    // ---- phase 2: warp w -> full lineup of row (r0 + w) ----
    {
        const float* pq = pqs + w * QDIM;
        const float* tq = tqs + w * QDIM;
        float* ln       = lined + w * QDIM;
        unsigned char* mt = match + w * QDIM;

        uint4 WT = ((const uint4*)(maskT + w * 128))[l];
        uint4 WP = ((const uint4*)(maskP + w * 128))[l];

        #pragma unroll
        for (int j = 0; j < 8; j++) {
            ln[l * 8 + j] = NEG_FILL;
            mt[l * 8 + j] = 0;
        }

        // transpose ballot-order -> row-major words
        unsigned mT[4], mP[4];
        #pragma unroll
        for (int k = 0; k < 4; k++) {
            unsigned sh = 8 * k;
            mT[k] = spread4((WT.x >> sh) & 0xFFu)
                  | (spread4((WT.y >> sh) & 0xFFu) << 1)
                  | (spread4((WT.z >> sh) & 0xFFu) << 2)
                  | (spread4((WT.w >> sh) & 0xFFu) << 3);
            mP[k] = spread4((WP.x >> sh) & 0xFFu)
                  | (spread4((WP.y >> sh) & 0xFFu) << 1)
                  | (spread4((WP.z >> sh) & 0xFFu) << 2)
                  | (spread4((WP.w >> sh) & 0xFFu) << 3);
        }

        int cT = 0, cP = 0;
        #pragma unroll
        for (int k = 0; k < 4; k++) { cT += __popc(mT[k]); cP += __popc(mP[k]); }
        int sTc = cT, sPc = cP;   // warp-inclusive scans
        #pragma unroll
        for (int o = 1; o < 32; o <<= 1) {
            int vT = __shfl_up_sync(0xffffffffu, sTc, o);
            int vP = __shfl_up_sync(0xffffffffu, sPc, o);
            if (l >= o) { sTc += vT; sPc += vP; }
        }
        int tIdx  = sTc - cT;
        int pBase = sPc - cP;
        __syncwarp();

        // sparse scatter (ranks unique -> plain stores)
        #pragma unroll
        for (int k = 0; k < 4; k++) {
            unsigned m = mT[k], p = mP[k];
            while (m) {
                int bit = __ffs(m) - 1;
                m &= m - 1;
                if ((p >> bit) & 1u) {
                    int pi = pBase + __popc(p & ((1u << bit) - 1u));
                    if (pi < QDIM - 1 && tIdx < QDIM - 1) {
                        ln[tIdx] = pq[pi];
                        mt[tIdx] = 1;
                    }
                }
                tIdx++;
            }
            pBase += __popc(p);
        }
        __syncwarp();

        // logsumexp over lined[0..254] — PRECISE expf/logf (CE is x200 sensitive)
        float vals[8];
        float mx = -INFINITY;
        #pragma unroll
        for (int j = 0; j < 8; j++) {
            vals[j] = ln[l * 8 + j];
            mx = fmaxf(mx, vals[j]);          // slot 255 is NEG_FILL: harmless
        }
        mx = warpMax(mx);
        float es = 0.f;
        #pragma unroll
        for (int j = 0; j < 8; j++)
            if (l * 8 + j < QDIM - 1) es += expf(vals[j] - mx);
        es = warpSum(es);
        float lse = mx + logf(es);

        float wsum = 0.f, dot = 0.f;
        #pragma unroll
        for (int j = 0; j < 8; j++) {
            int idx = l * 8 + j;
            if (idx < QDIM - 1) {
                float wq = tq[idx] * (float)mt[idx];
                wsum += wq;
                dot  += wq * (vals[j] - lse);
            }
        }
        wsum = warpSum(wsum);
        dot  = warpSum(dot);

        if (l == 0) {
            rowCe[w]  = -dot / (wsum + 1e-10f);
            float dq = pq[QDIM - 1] - tq[QDIM - 1];
            rowMse[w] = dq * dq;
        }
    }

    // ---- block reduce BCE (double) + per-block partials + ticket ----
    double sBce = blockReduceSumD((double)accBce, shd);

    if (t == 0) {
        float ce = 0.f, ms = 0.f;
        #pragma unroll
        for (int i = 0; i < ROWS_PB; i++) { ce += rowCe[i]; ms += rowMse[i]; }
        g_lab[blockIdx.x] = (float)sBce;
        g_ce [blockIdx.x] = ce;
        g_mse[blockIdx.x] = ms;
        __threadfence();
        unsigned old = atomicAdd(&g_count, 1u);
        lastFlag = (old == (unsigned)(nblk - 1)) ? 1u : 0u;
    }
    __syncthreads();

    // ---- last block: final scalar reduce ----
    if (lastFlag) {
        __threadfence();
        double sLab = 0.0, sCe = 0.0, sMse = 0.0;
        for (int i = t; i < nblk; i += 256) {
            sLab += (double)g_lab[i];
            sCe  += (double)g_ce[i];
            sMse += (double)g_mse[i];
        }
        sLab = blockReduceSumD(sLab, shd);
        sCe  = blockReduceSumD(sCe,  shd);
        sMse = blockReduceSumD(sMse, shd);
        if (t == 0) {
            double loss_labels = sLab / ((double)B * (double)NROW);
            double loss_ce     = sCe / (double)(QDIM - 1);
            double loss_mse    = sMse / (double)B;
            out[0] = (float)loss_labels;
            out[1] = (float)(loss_ce * 200.0 + loss_mse);
            g_count = 0;   // reset for next graph replay
        }
    }
}

extern "C" void kernel_launch(void* const* d_in, const int* in_sizes, int n_in,
                              void* d_out, int out_size) {
    const float* pred_legal   = (const float*)d_in[0];
    const float* pred_q       = (const float*)d_in[1];
    const float* target_legal = (const float*)d_in[2];
    const float* target_q     = (const float*)d_in[3];
    float* out = (float*)d_out;

    int B = in_sizes[1] / QDIM;      // 4096
    int nblk = B / ROWS_PB;          // 512

    crit_kernel<<<nblk, 256>>>(pred_legal, target_legal,
                               (const float4*)pred_q,
                               (const float4*)target_q,
                               out, B, nblk);
}

// round 12
// speedup vs baseline: 2.2059x; 1.2207x over previous
#include <cuda_runtime.h>
#include <math.h>
#include <cstdint>

#define NROW 4096          // 64*64 legality cells per board
#define QDIM 256           // quality vector length
#define NEG_FILL -1000000.0f
#define EOS_COEF 0.25f
#define ROWS_PB 4          // rows per block; 2 warps stream each row
#define MAXBLK 4096

// Per-block partials + ticket (static globals — no allocation)
__device__ float    g_lab[MAXBLK];
__device__ float    g_ce [MAXBLK];
__device__ float    g_mse[MAXBLK];
__device__ unsigned g_count;   // zero-init; last block resets to 0

// spread 8 bits to every 4th bit position (bit i -> bit 4i)
__device__ __forceinline__ unsigned spread4(unsigned x) {
    x = (x | (x << 12)) & 0x000F000Fu;
    x = (x | (x << 6))  & 0x03030303u;
    x = (x | (x << 3))  & 0x11111111u;
    return x;
}
__device__ __forceinline__ float warpSum(float v) {
    #pragma unroll
    for (int o = 16; o; o >>= 1) v += __shfl_xor_sync(0xffffffffu, v, o);
    return v;
}
__device__ __forceinline__ float warpMax(float v) {
    #pragma unroll
    for (int o = 16; o; o >>= 1) v = fmaxf(v, __shfl_xor_sync(0xffffffffu, v, o));
    return v;
}
__device__ __forceinline__ double blockReduceSumD(double v, double* shd) {
    int lane = threadIdx.x & 31, warp = threadIdx.x >> 5;
    #pragma unroll
    for (int o = 16; o; o >>= 1) v += __shfl_down_sync(0xffffffffu, v, o);
    if (lane == 0) shd[warp] = v;
    __syncthreads();
    if (warp == 0) {
        v = (lane < 8) ? shd[lane] : 0.0;
        #pragma unroll
        for (int o = 4; o; o >>= 1) v += __shfl_down_sync(0xffffffffu, v, o);
        if (lane == 0) shd[0] = v;
    }
    __syncthreads();
    double r = shd[0];
    __syncthreads();
    return r;
}

// One block = 4 rows, 8 warps. Phase 1: warp w streams half (w&1) of row (w>>1)
// — barrier-free, lane-coalesced. Phase 2: warps 0-3 run the 4 lineups in parallel.
__global__ __launch_bounds__(256, 8) void crit_kernel(
    const float* __restrict__ pl,     // pred_legal  [B,4096]
    const float* __restrict__ tl,     // target_legal[B,4096]
    const float4* __restrict__ pq4,   // pred_q      [B*64] float4
    const float4* __restrict__ tq4,   // target_q    [B*64] float4
    float* __restrict__ out, int B, int nblk)
{
    const int r0 = blockIdx.x * ROWS_PB;
    const int w = threadIdx.x >> 5, l = threadIdx.x & 31;
    const int t = threadIdx.x;

    __shared__ alignas(16) unsigned maskT[ROWS_PB * 128];   // 2 KB (ballot order)
    __shared__ alignas(16) unsigned maskP[ROWS_PB * 128];   // 2 KB
    __shared__ alignas(16) float pqs[ROWS_PB * QDIM];       // 4 KB
    __shared__ alignas(16) float tqs[ROWS_PB * QDIM];       // 4 KB
    __shared__ alignas(16) float lined[ROWS_PB * QDIM];     // 4 KB
    __shared__ unsigned char match[ROWS_PB * QDIM];         // 1 KB
    __shared__ float rowCe[ROWS_PB], rowMse[ROWS_PB];
    __shared__ double shd[8];
    __shared__ unsigned lastFlag;

    // ---- stage quality vectors: 4 rows x 64 float4 = 256 float4, 1/thread ----
    {
        ((float4*)pqs)[t] = __ldg(pq4 + (size_t)r0 * 64 + t);
        ((float4*)tqs)[t] = __ldg(tq4 + (size_t)r0 * 64 + t);
    }

    // ---- phase 1: warp w streams half (w&1) of row (w>>1): 2048 elements ----
    const int myRow  = w >> 1;
    const int myHalf = w & 1;
    float accBce = 0.f;
    {
        const size_t rowOff = (size_t)(r0 + myRow) * 1024 + myHalf * 512; // float4
        const float4* pl4 = (const float4*)pl + rowOff;
        const float4* tl4 = (const float4*)tl + rowOff;
        #pragma unroll 4
        for (int i = 0; i < 16; i++) {
            int idx = i * 32 + l;                       // lane-coalesced
            float4 pv = __ldg(pl4 + idx);
            float4 tv = __ldg(tl4 + idx);
            float px[4] = {pv.x, pv.y, pv.z, pv.w};
            float tx[4] = {tv.x, tv.y, tv.z, tv.w};
            bool pt[4], pp[4];
            #pragma unroll
            for (int j = 0; j < 4; j++) {
                float x = px[j], tg = tx[j];
                float sp  = __logf(1.f + __expf(-fabsf(x)));   // fast ok in BCE (R3)
                float bce = fmaxf(x, 0.f) - x * tg + sp;
                accBce += (tg == 0.f ? EOS_COEF : 1.f) * bce;
                pt[j] = (tg == 1.f);
                pp[j] = (x  > 0.f);
            }
            unsigned bT0 = __ballot_sync(0xffffffffu, pt[0]);
            unsigned bT1 = __ballot_sync(0xffffffffu, pt[1]);
            unsigned bT2 = __ballot_sync(0xffffffffu, pt[2]);
            unsigned bT3 = __ballot_sync(0xffffffffu, pt[3]);
            unsigned bP0 = __ballot_sync(0xffffffffu, pp[0]);
            unsigned bP1 = __ballot_sync(0xffffffffu, pp[1]);
            unsigned bP2 = __ballot_sync(0xffffffffu, pp[2]);
            unsigned bP3 = __ballot_sync(0xffffffffu, pp[3]);
            // chunk c = myHalf*16 + i of row myRow; word c*4+j, bit l
            int base = myRow * 128 + (myHalf * 16 + i) * 4;
            if (l < 4) {
                unsigned vT = (l == 0) ? bT0 : (l == 1) ? bT1 : (l == 2) ? bT2 : bT3;
                maskT[base + l] = vT;
            } else if (l < 8) {
                int j = l - 4;
                unsigned vP = (j == 0) ? bP0 : (j == 1) ? bP1 : (j == 2) ? bP2 : bP3;
                maskP[base + j] = vP;
            }
        }
    }
    __syncthreads();   // masks + staged quality vectors visible

    // ---- phase 2: warps 0-3 -> full lineup of row (r0 + w) ----
    if (w < ROWS_PB) {
        const float* pq = pqs + w * QDIM;
        const float* tq = tqs + w * QDIM;
        float* ln       = lined + w * QDIM;
        unsigned char* mt = match + w * QDIM;

        uint4 WT = ((const uint4*)(maskT + w * 128))[l];
        uint4 WP = ((const uint4*)(maskP + w * 128))[l];

        #pragma unroll
        for (int j = 0; j < 8; j++) {
            ln[l * 8 + j] = NEG_FILL;
            mt[l * 8 + j] = 0;
        }

        // transpose ballot-order -> row-major words
        unsigned mT[4], mP[4];
        #pragma unroll
        for (int k = 0; k < 4; k++) {
            unsigned sh = 8 * k;
            mT[k] = spread4((WT.x >> sh) & 0xFFu)
                  | (spread4((WT.y >> sh) & 0xFFu) << 1)
                  | (spread4((WT.z >> sh) & 0xFFu) << 2)
                  | (spread4((WT.w >> sh) & 0xFFu) << 3);
            mP[k] = spread4((WP.x >> sh) & 0xFFu)
                  | (spread4((WP.y >> sh) & 0xFFu) << 1)
                  | (spread4((WP.z >> sh) & 0xFFu) << 2)
                  | (spread4((WP.w >> sh) & 0xFFu) << 3);
        }

        int cT = 0, cP = 0;
        #pragma unroll
        for (int k = 0; k < 4; k++) { cT += __popc(mT[k]); cP += __popc(mP[k]); }
        int sTc = cT, sPc = cP;   // warp-inclusive scans
        #pragma unroll
        for (int o = 1; o < 32; o <<= 1) {
            int vT = __shfl_up_sync(0xffffffffu, sTc, o);
            int vP = __shfl_up_sync(0xffffffffu, sPc, o);
            if (l >= o) { sTc += vT; sPc += vP; }
        }
        int tIdx  = sTc - cT;
        int pBase = sPc - cP;
        __syncwarp();

        // sparse scatter (ranks unique -> plain stores)
        #pragma unroll
        for (int k = 0; k < 4; k++) {
            unsigned m = mT[k], p = mP[k];
            while (m) {
                int bit = __ffs(m) - 1;
                m &= m - 1;
                if ((p >> bit) & 1u) {
                    int pi = pBase + __popc(p & ((1u << bit) - 1u));
                    if (pi < QDIM - 1 && tIdx < QDIM - 1) {
                        ln[tIdx] = pq[pi];
                        mt[tIdx] = 1;
                    }
                }
                tIdx++;
            }
            pBase += __popc(p);
        }
        __syncwarp();

        // logsumexp over lined[0..254] — PRECISE expf/logf (CE is x200 sensitive)
        float vals[8];
        float mx = -INFINITY;
        #pragma unroll
        for (int j = 0; j < 8; j++) {
            vals[j] = ln[l * 8 + j];
            mx = fmaxf(mx, vals[j]);          // slot 255 is NEG_FILL: harmless
        }
        mx = warpMax(mx);
        float es = 0.f;
        #pragma unroll
        for (int j = 0; j < 8; j++)
            if (l * 8 + j < QDIM - 1) es += expf(vals[j] - mx);
        es = warpSum(es);
        float lse = mx + logf(es);

        float wsum = 0.f, dot = 0.f;
        #pragma unroll
        for (int j = 0; j < 8; j++) {
            int idx = l * 8 + j;
            if (idx < QDIM - 1) {
                float wq = tq[idx] * (float)mt[idx];
                wsum += wq;
                dot  += wq * (vals[j] - lse);
            }
        }
        wsum = warpSum(wsum);
        dot  = warpSum(dot);

        if (l == 0) {
            rowCe[w]  = -dot / (wsum + 1e-10f);
            float dq = pq[QDIM - 1] - tq[QDIM - 1];
            rowMse[w] = dq * dq;
        }
    }

    // ---- block reduce BCE (double) + per-block partials + ticket ----
    double sBce = blockReduceSumD((double)accBce, shd);

    if (t == 0) {
        float ce = 0.f, ms = 0.f;
        #pragma unroll
        for (int i = 0; i < ROWS_PB; i++) { ce += rowCe[i]; ms += rowMse[i]; }
        g_lab[blockIdx.x] = (float)sBce;
        g_ce [blockIdx.x] = ce;
        g_mse[blockIdx.x] = ms;
        __threadfence();
        unsigned old = atomicAdd(&g_count, 1u);
        lastFlag = (old == (unsigned)(nblk - 1)) ? 1u : 0u;
    }
    __syncthreads();

    // ---- last block: final scalar reduce ----
    if (lastFlag) {
        __threadfence();
        double sLab = 0.0, sCe = 0.0, sMse = 0.0;
        for (int i = t; i < nblk; i += 256) {
            sLab += (double)g_lab[i];
            sCe  += (double)g_ce[i];
            sMse += (double)g_mse[i];
        }
        sLab = blockReduceSumD(sLab, shd);
        sCe  = blockReduceSumD(sCe,  shd);
        sMse = blockReduceSumD(sMse, shd);
        if (t == 0) {
            double loss_labels = sLab / ((double)B * (double)NROW);
            double loss_ce     = sCe / (double)(QDIM - 1);
            double loss_mse    = sMse / (double)B;
            out[0] = (float)loss_labels;
            out[1] = (float)(loss_ce * 200.0 + loss_mse);
            g_count = 0;   // reset for next graph replay
        }
    }
}

extern "C" void kernel_launch(void* const* d_in, const int* in_sizes, int n_in,
                              void* d_out, int out_size) {
    const float* pred_legal   = (const float*)d_in[0];
    const float* pred_q       = (const float*)d_in[1];
    const float* target_legal = (const float*)d_in[2];
    const float* target_q     = (const float*)d_in[3];
    float* out = (float*)d_out;

    int B = in_sizes[1] / QDIM;      // 4096
    int nblk = B / ROWS_PB;          // 1024

    crit_kernel<<<nblk, 256>>>(pred_legal, target_legal,
                               (const float4*)pred_q,
                               (const float4*)target_q,
                               out, B, nblk);
}